// round 8
// baseline (speedup 1.0000x reference)
#include <cuda_runtime.h>
#include <cstdint>

#define S 4096
#define DM 1024
#define H 16
#define HD 64
#define WIN 512
#define NK 3072

// ---------------- device scratch (frag-major layouts) ----------------------
// g_xc : a-frag  [mt(256)][k8(128)][lane][4]
// g_wc : b-frag  [nt8(384)][k16(64)][lane][4]
// g_q2 : a-frag  [h][mt(256)][k8(8)][lane][4]        (k-dim = head dim d)
// g_k2 : b-frag  [h][nt8(512)][d16(4)][lane][4]      (k-dim = d, n = keys)
// g_v2 : b-frag  [h][t(64)][dt8(8)][k16(4)][lane][4] (k-dim = keys, n = d)
__device__ float g_xc[S * DM];
__device__ float g_wc[DM * NK];
__device__ float g_q2[H * S * HD];
__device__ float g_k2[H * S * HD];
__device__ float g_v2[H * S * HD];

// ---------------- helpers ---------------------------------------------------
__device__ __forceinline__ float tf32_rna(float x) {
    float r;
    asm("cvt.rna.tf32.f32 %0, %1;" : "=f"(r) : "f"(x));
    return r;
}
__device__ __forceinline__ uint32_t smem_u32(const void* p) {
    uint32_t a;
    asm("{ .reg .u64 t; cvta.to.shared.u64 t, %1; cvt.u32.u64 %0, t; }"
        : "=r"(a) : "l"(p));
    return a;
}
__device__ __forceinline__ void cp16(uint32_t dst, const void* src) {
    asm volatile("cp.async.cg.shared.global [%0], [%1], 16;" :: "r"(dst), "l"(src));
}
__device__ __forceinline__ void cp_commit() {
    asm volatile("cp.async.commit_group;" ::: "memory");
}
__device__ __forceinline__ void cp_wait0() { asm volatile("cp.async.wait_group 0;" ::: "memory"); }
__device__ __forceinline__ void cp_wait1() { asm volatile("cp.async.wait_group 1;" ::: "memory"); }
__device__ __forceinline__ void cp_wait2() { asm volatile("cp.async.wait_group 2;" ::: "memory"); }
__device__ __forceinline__ void mma1688(float* c, const uint32_t* a, const uint32_t* b) {
    asm volatile(
        "mma.sync.aligned.m16n8k8.row.col.f32.tf32.tf32.f32 "
        "{%0,%1,%2,%3}, {%4,%5,%6,%7}, {%8,%9}, {%0,%1,%2,%3};"
        : "+f"(c[0]), "+f"(c[1]), "+f"(c[2]), "+f"(c[3])
        : "r"(a[0]), "r"(a[1]), "r"(a[2]), "r"(a[3]), "r"(b[0]), "r"(b[1]));
}

// ---------------- prep: round to tf32 + frag-major scatter ------------------
__global__ __launch_bounds__(256) void prep_x(const float* __restrict__ x) {
    int row = blockIdx.x;
    int k0 = threadIdx.x * 4;
    float4 v = *(const float4*)&x[(size_t)row * DM + k0];
    float vv[4] = {tf32_rna(v.x), tf32_rna(v.y), tf32_rna(v.z), tf32_rna(v.w)};
    int base = ((row >> 4) * 128 + (k0 >> 3)) * 128;
    int s = 2 * ((k0 >> 2) & 1) + ((row >> 3) & 1);
    int l0 = (row & 7) * 4;
#pragma unroll
    for (int t = 0; t < 4; t++) g_xc[base + (l0 + t) * 4 + s] = vv[t];
}
__global__ __launch_bounds__(256) void prep_w(const float* __restrict__ w) {
    int b = blockIdx.x;
    int k = b / 3;
    int n0 = (b % 3) * 1024 + threadIdx.x * 4;
    float4 v = *(const float4*)&w[(size_t)k * NK + n0];
    float vv[4] = {tf32_rna(v.x), tf32_rna(v.y), tf32_rna(v.z), tf32_rna(v.w)};
    int base = ((n0 >> 3) * 64 + (k >> 4)) * 128;
    int s = ((k >> 3) & 1) * 2 + ((k >> 2) & 1);
    int lc = k & 3;
#pragma unroll
    for (int t = 0; t < 4; t++) {
        int n = n0 + t;
        g_wc[base + ((n & 7) * 4 + lc) * 4 + s] = vv[t];
    }
}

// ---------------- tf32 mma.sync KQV GEMM, 256x128 tile ----------------------
// 8 warps as 4x2; warp tile 64x64 (4 m16 x 8 n8). BK=16, 4 stages.
#define GSTAGE_F 6144                 // A 4096 + B 2048 floats
#define GNSTAGES 4
#define GEMM_SMEM (GNSTAGES * GSTAGE_F * 4)   // 98304

__device__ __forceinline__ void g_load_stage(uint32_t sb, int st, int kt16, int tid,
                                             int mt0, int n8b) {
    uint32_t ab = sb + st * (GSTAGE_F * 4);
    uint32_t bb = ab + 4096 * 4;
#pragma unroll
    for (int u = 0; u < 4; u++) {                  // A: 1024 chunks (16 m16 x 2 k8)
        int c = tid + u * 256;
        int mti = c >> 6, rem = c & 63;
        int k8l = rem >> 5, cb = rem & 31;
        cp16(ab + ((mti * 2 + k8l) * 32 + cb) * 16,
             g_xc + (size_t)((mt0 + mti) * 128 + kt16 * 2 + k8l) * 128 + cb * 4);
    }
#pragma unroll
    for (int u = 0; u < 2; u++) {                  // B: 512 chunks (16 nt8)
        int c = tid + u * 256;
        int nt8l = c >> 5, cb = c & 31;
        cp16(bb + (nt8l * 32 + cb) * 16,
             g_wc + (size_t)((n8b + nt8l) * 64 + kt16) * 128 + cb * 4);
    }
}

__global__ __launch_bounds__(256, 1) void kqv_gemm_mma() {
    extern __shared__ __align__(16) uint8_t smem_raw[];
    uint32_t sb = smem_u32(smem_raw);
    const int tid = threadIdx.x;
    const int warp = tid >> 5, lane = tid & 31;
    const int lr = lane >> 2, lc = lane & 3;
    const int wm = warp >> 1, wn = warp & 1;
    const int m0 = blockIdx.y * 256;
    const int n0 = blockIdx.x * 128;
    const int mt0 = blockIdx.y * 16;
    const int n8b = blockIdx.x * 16;

    float c[4][8][4];
#pragma unroll
    for (int i = 0; i < 4; i++)
#pragma unroll
        for (int j = 0; j < 8; j++)
#pragma unroll
            for (int t = 0; t < 4; t++) c[i][j][t] = 0.f;

#pragma unroll
    for (int s = 0; s < GNSTAGES - 1; s++) {
        g_load_stage(sb, s, s, tid, mt0, n8b);
        cp_commit();
    }
    cp_wait2();
    __syncthreads();

    for (int kt = 0; kt < 64; kt++) {
        int st = kt & (GNSTAGES - 1);
        const float* As = (const float*)(smem_raw + st * (GSTAGE_F * 4));
        const float* Bs = As + 4096;
        uint32_t a[4][2][4], b[8][4];
#pragma unroll
        for (int i = 0; i < 4; i++)
#pragma unroll
            for (int k8 = 0; k8 < 2; k8++) {
                const uint4 v =
                    *(const uint4*)&As[((wm * 4 + i) * 2 + k8) * 128 + lane * 4];
                a[i][k8][0] = v.x; a[i][k8][1] = v.y; a[i][k8][2] = v.z; a[i][k8][3] = v.w;
            }
#pragma unroll
        for (int j = 0; j < 8; j++) {
            const uint4 v = *(const uint4*)&Bs[(wn * 8 + j) * 128 + lane * 4];
            b[j][0] = v.x; b[j][1] = v.y; b[j][2] = v.z; b[j][3] = v.w;
        }
#pragma unroll
        for (int k8 = 0; k8 < 2; k8++)
#pragma unroll
            for (int i = 0; i < 4; i++)
#pragma unroll
                for (int j = 0; j < 8; j++)
                    mma1688(c[i][j], a[i][k8], &b[j][k8 * 2]);
        __syncthreads();
        int nk = kt + GNSTAGES - 1;
        if (nk < 64) g_load_stage(sb, nk & (GNSTAGES - 1), nk, tid, mt0, n8b);
        cp_commit();
        cp_wait2();
        __syncthreads();
    }

    // ---- epilogue: scatter into frag-major g_q2/g_k2/g_v2 ----
    const int gc0 = n0 + wn * 64;
    const int chunk = gc0 >> 10;
    const int h = (gc0 & 1023) >> 6;
    const int mbase = m0 + wm * 64;

#pragma unroll
    for (int i = 0; i < 4; i++) {
#pragma unroll
        for (int j = 0; j < 8; j++) {
            float v0 = tf32_rna(c[i][j][0]), v1 = tf32_rna(c[i][j][1]);
            float v2 = tf32_rna(c[i][j][2]), v3 = tf32_rna(c[i][j][3]);
            int d = j * 8 + 2 * lc;
            int r = mbase + i * 16 + lr;
            if (chunk == 1) {                    // Q : a-frag
                int base = ((h * 256 + (r >> 4)) * 8 + j) * 128;
                int lp = lr * 4 + (d & 3);
                int k4 = (lc >> 1) & 1;
                *(float2*)&g_q2[base + lp * 4 + 2 * k4] = make_float2(v0, v2);
                *(float2*)&g_q2[base + (lp + 1) * 4 + 2 * k4] = make_float2(v1, v3);
            } else if (chunk == 0) {             // K : b-frag over d
                int d16 = j >> 1;
                int s = (j & 1) * 2 + (lc >> 1);
                int lp = lr * 4 + (d & 3);
                int ba = ((h * 512 + (r >> 3)) * 4 + d16) * 128;
                int bb = ((h * 512 + ((r + 8) >> 3)) * 4 + d16) * 128;
                g_k2[ba + lp * 4 + s] = v0;
                g_k2[ba + (lp + 1) * 4 + s] = v1;
                g_k2[bb + lp * 4 + s] = v2;
                g_k2[bb + (lp + 1) * 4 + s] = v3;
            } else {                             // V : b-frag transposed (k=keys)
#pragma unroll
                for (int rb = 0; rb < 2; rb++) {
                    int m = r + rb * 8;
                    float va = rb ? v2 : v0, vb = rb ? v3 : v1;
                    int base = (((h * 64 + (m >> 6)) * 8 + j) * 4 + ((m >> 4) & 3)) * 128;
                    int s = ((m >> 3) & 1) * 2 + ((m >> 2) & 1);
                    g_v2[base + ((d & 7) * 4 + (m & 3)) * 4 + s] = va;
                    g_v2[base + (((d + 1) & 7) * 4 + (m & 3)) * 4 + s] = vb;
                }
            }
        }
    }
}

// ---------------------------------------------------------------------------
// Tensor-core flash attention, frag-major, ILP-ordered MMAs.
// ---------------------------------------------------------------------------
#define KV_OFF(s) ((s) * 8192)
#define P_OFF 16384
#define ATTN_SMEM ((16384 + 8192) * 4)
#define SCL 0.03125f

__device__ __forceinline__ void a_load_kv(uint32_t sb, int s, int kt, int tid,
                                          const float* __restrict__ kb,
                                          const float* __restrict__ vb) {
    uint32_t kd = sb + KV_OFF(s) * 4;
    uint32_t vd = kd + 4096 * 4;
    const float* kg = kb + (size_t)kt * 4096;
    const float* vg = vb + (size_t)kt * 4096;
#pragma unroll
    for (int u = 0; u < 4; u++) {
        int c = tid + u * 256;
        cp16(kd + c * 16, kg + c * 4);
        cp16(vd + c * 16, vg + c * 4);
    }
}

__global__ __launch_bounds__(256, 1) void attn_tc(float* __restrict__ out) {
    extern __shared__ __align__(16) uint8_t smem_raw[];
    float* sm = (float*)smem_raw;
    uint32_t sb = smem_u32(smem_raw);

    const int tid = threadIdx.x;
    const int w = tid >> 5, lane = tid & 31;
    const int lr = lane >> 2, lc = lane & 3;
    const int qt = blockIdx.x;
    const int h = blockIdx.y;
    const int q0 = qt * 128;

    const float slope = exp2f(-0.5f * (float)(h + 1));
    const float* __restrict__ kbh = g_k2 + (size_t)h * S * HD;
    const float* __restrict__ vbh = g_v2 + (size_t)h * S * HD;

    const int kt0 = (qt >= 4) ? (2 * qt - 8) : 0;
    const int kt1 = 2 * qt + 1;

    a_load_kv(sb, 0, kt0, tid, kbh, vbh);
    cp_commit();

    uint32_t qa[8][4];
    {
        const float* qb = g_q2 + (size_t)((h * 256 + qt * 8 + w) * 8) * 128;
#pragma unroll
        for (int k8 = 0; k8 < 8; k8++) {
            uint4 v = *(const uint4*)&qb[k8 * 128 + lane * 4];
            qa[k8][0] = v.x; qa[k8][1] = v.y; qa[k8][2] = v.z; qa[k8][3] = v.w;
        }
    }

    float o[8][4];
    float m0r = -1e30f, m1r = -1e30f, l0 = 0.f, l1 = 0.f;
#pragma unroll
    for (int nt = 0; nt < 8; nt++)
#pragma unroll
        for (int t = 0; t < 4; t++) o[nt][t] = 0.f;

    const int i0 = q0 + w * 16 + lr;
    const int i1 = i0 + 8;
    float* Pw = sm + P_OFF + w * 1024;
    const float s8 = slope * 8.f;

    for (int kt = kt0; kt <= kt1; kt++) {
        int st = (kt - kt0) & 1;
        if (kt < kt1) {
            a_load_kv(sb, st ^ 1, kt + 1, tid, kbh, vbh);
            cp_commit();
            cp_wait1();
        } else {
            cp_wait0();
        }
        __syncthreads();

        const float* Ks = sm + KV_OFF(st);
        const float* Vs = Ks + 4096;
        const int kb = kt * 64;

        // ---- S = Q K^T : k16 outer, 8 independent accum chains inner ----
        float sc[8][4];
#pragma unroll
        for (int nt = 0; nt < 8; nt++)
#pragma unroll
            for (int t = 0; t < 4; t++) sc[nt][t] = 0.f;
#pragma unroll
        for (int k16 = 0; k16 < 4; k16++) {
            uint32_t bk[8][4];
#pragma unroll
            for (int nt = 0; nt < 8; nt++) {
                uint4 v = *(const uint4*)&Ks[(nt * 4 + k16) * 128 + lane * 4];
                bk[nt][0] = v.x; bk[nt][1] = v.y; bk[nt][2] = v.z; bk[nt][3] = v.w;
            }
#pragma unroll
            for (int nt = 0; nt < 8; nt++) mma1688(sc[nt], qa[k16 * 2], &bk[nt][0]);
#pragma unroll
            for (int nt = 0; nt < 8; nt++) mma1688(sc[nt], qa[k16 * 2 + 1], &bk[nt][2]);
        }

        // ---- bias/mask + online softmax ----
        const bool full = (kt <= 2 * qt - 1) && (kt >= 2 * qt - 6);
        float mx0 = -3e38f, mx1 = -3e38f;
        if (full) {
            float bias = slope * (float)(kb + 2 * lc - i0);
#pragma unroll
            for (int nt = 0; nt < 8; nt++) {
                sc[nt][0] = fmaf(sc[nt][0], SCL, bias);
                sc[nt][1] = fmaf(sc[nt][1], SCL, bias + slope);
                sc[nt][2] = fmaf(sc[nt][2], SCL, bias - s8);
                sc[nt][3] = fmaf(sc[nt][3], SCL, bias - s8 + slope);
                mx0 = fmaxf(mx0, fmaxf(sc[nt][0], sc[nt][1]));
                mx1 = fmaxf(mx1, fmaxf(sc[nt][2], sc[nt][3]));
                bias += s8;
            }
        } else {
#pragma unroll
            for (int nt = 0; nt < 8; nt++) {
                int j0 = kb + nt * 8 + 2 * lc;
                int d00 = i0 - j0;
                sc[nt][0] = (d00 >= 0 && d00 <= WIN)
                                ? fmaf(sc[nt][0], SCL, slope * (float)(-d00)) : -3e38f;
                int d01 = d00 - 1;
                sc[nt][1] = (d01 >= 0 && d01 <= WIN)
                                ? fmaf(sc[nt][1], SCL, slope * (float)(-d01)) : -3e38f;
                int d10 = i1 - j0;
                sc[nt][2] = (d10 >= 0 && d10 <= WIN)
                                ? fmaf(sc[nt][2], SCL, slope * (float)(-d10)) : -3e38f;
                int d11 = d10 - 1;
                sc[nt][3] = (d11 >= 0 && d11 <= WIN)
                                ? fmaf(sc[nt][3], SCL, slope * (float)(-d11)) : -3e38f;
                mx0 = fmaxf(mx0, fmaxf(sc[nt][0], sc[nt][1]));
                mx1 = fmaxf(mx1, fmaxf(sc[nt][2], sc[nt][3]));
            }
        }
        mx0 = fmaxf(mx0, __shfl_xor_sync(0xffffffffu, mx0, 1));
        mx0 = fmaxf(mx0, __shfl_xor_sync(0xffffffffu, mx0, 2));
        mx1 = fmaxf(mx1, __shfl_xor_sync(0xffffffffu, mx1, 1));
        mx1 = fmaxf(mx1, __shfl_xor_sync(0xffffffffu, mx1, 2));

        float mn0 = fmaxf(m0r, mx0), mn1 = fmaxf(m1r, mx1);
        float al0 = __expf(m0r - mn0), al1 = __expf(m1r - mn1);
        m0r = mn0; m1r = mn1;

        const int lp = lr * 4 + ((2 * lc) & 3);
        const int k4b = 2 * ((lc >> 1) & 1);
        float rs0 = 0.f, rs1 = 0.f;
#pragma unroll
        for (int nt = 0; nt < 8; nt++) {
            float p00 = tf32_rna(__expf(sc[nt][0] - mn0));
            float p01 = tf32_rna(__expf(sc[nt][1] - mn0));
            float p10 = tf32_rna(__expf(sc[nt][2] - mn1));
            float p11 = tf32_rna(__expf(sc[nt][3] - mn1));
            rs0 += p00 + p01;
            rs1 += p10 + p11;
            *(float2*)&Pw[nt * 128 + lp * 4 + k4b] = make_float2(p00, p10);
            *(float2*)&Pw[nt * 128 + (lp + 1) * 4 + k4b] = make_float2(p01, p11);
        }
        rs0 += __shfl_xor_sync(0xffffffffu, rs0, 1);
        rs0 += __shfl_xor_sync(0xffffffffu, rs0, 2);
        rs1 += __shfl_xor_sync(0xffffffffu, rs1, 1);
        rs1 += __shfl_xor_sync(0xffffffffu, rs1, 2);
        l0 = l0 * al0 + rs0;
        l1 = l1 * al1 + rs1;
#pragma unroll
        for (int nt = 0; nt < 8; nt++) {
            o[nt][0] *= al0; o[nt][1] *= al0;
            o[nt][2] *= al1; o[nt][3] *= al1;
        }
        __syncwarp();

        uint32_t pa[8][4];
#pragma unroll
        for (int k8 = 0; k8 < 8; k8++) {
            uint4 v = *(const uint4*)&Pw[k8 * 128 + lane * 4];
            pa[k8][0] = v.x; pa[k8][1] = v.y; pa[k8][2] = v.z; pa[k8][3] = v.w;
        }

        // ---- O += P V : k16 outer, independent chains inner ----
#pragma unroll
        for (int k16 = 0; k16 < 4; k16++) {
            uint32_t vk[8][4];
#pragma unroll
            for (int nt = 0; nt < 8; nt++) {
                uint4 v = *(const uint4*)&Vs[(nt * 4 + k16) * 128 + lane * 4];
                vk[nt][0] = v.x; vk[nt][1] = v.y; vk[nt][2] = v.z; vk[nt][3] = v.w;
            }
#pragma unroll
            for (int nt = 0; nt < 8; nt++) mma1688(o[nt], pa[k16 * 2], &vk[nt][0]);
#pragma unroll
            for (int nt = 0; nt < 8; nt++) mma1688(o[nt], pa[k16 * 2 + 1], &vk[nt][2]);
        }
        __syncthreads();
    }

    // ---- normalize + write ----
    float inv0 = 1.f / l0, inv1 = 1.f / l1;
    float* o0 = out + (size_t)i0 * DM + h * HD;
    float* o1 = out + (size_t)i1 * DM + h * HD;
#pragma unroll
    for (int nt = 0; nt < 8; nt++) {
        *(float2*)&o0[nt * 8 + 2 * lc] = make_float2(o[nt][0] * inv0, o[nt][1] * inv0);
        *(float2*)&o1[nt * 8 + 2 * lc] = make_float2(o[nt][2] * inv1, o[nt][3] * inv1);
    }
}

// ---------------------------------------------------------------------------
extern "C" void kernel_launch(void* const* d_in, const int* in_sizes, int n_in,
                              void* d_out, int out_size) {
    const float* x = (const float*)d_in[0];
    const float* w = (const float*)d_in[1];
    if (n_in >= 2 && in_sizes[0] == DM * NK && in_sizes[1] == S * DM) {
        const float* t = x; x = w; w = t;
    }
    float* out = (float*)d_out;

    static int attr_set = 0;
    if (!attr_set) {
        cudaFuncSetAttribute(kqv_gemm_mma, cudaFuncAttributeMaxDynamicSharedMemorySize,
                             GEMM_SMEM);
        cudaFuncSetAttribute(attn_tc, cudaFuncAttributeMaxDynamicSharedMemorySize,
                             ATTN_SMEM);
        attr_set = 1;
    }

    prep_x<<<4096, 256>>>(x);
    prep_w<<<3072, 256>>>(w);

    dim3 ggrid(NK / 128, S / 256);       // 24 x 16
    kqv_gemm_mma<<<ggrid, 256, GEMM_SMEM>>>();

    dim3 agrid(S / 128, H);
    attn_tc<<<agrid, 256, ATTN_SMEM>>>(out);
}

// round 10
// speedup vs baseline: 1.1030x; 1.1030x over previous
#include <cuda_runtime.h>
#include <cstdint>

#define S 4096
#define DM 1024
#define H 16
#define HD 64
#define WIN 512
#define NK 3072

// ---------------- device scratch (frag-major layouts) ----------------------
// g_xc : a-frag  [mt(256)][k8(128)][lane][4]
// g_wc : b-frag  [nt8(384)][k16(64)][lane][4]
// g_q2 : a-frag  [h][mt(256)][k8(8)][lane][4]        (k-dim = head dim d)
// g_k2 : b-frag  [h][nt8(512)][d16(4)][lane][4]      (k-dim = d, n = keys)
// g_v2 : b-frag  [h][t(64)][dt8(8)][k16(4)][lane][4] (k-dim = keys, n = d)
__device__ float g_xc[S * DM];
__device__ float g_wc[DM * NK];
__device__ float g_q2[H * S * HD];
__device__ float g_k2[H * S * HD];
__device__ float g_v2[H * S * HD];

// ---------------- helpers ---------------------------------------------------
__device__ __forceinline__ float tf32_rna(float x) {
    float r;
    asm("cvt.rna.tf32.f32 %0, %1;" : "=f"(r) : "f"(x));
    return r;
}
__device__ __forceinline__ uint32_t smem_u32(const void* p) {
    uint32_t a;
    asm("{ .reg .u64 t; cvta.to.shared.u64 t, %1; cvt.u32.u64 %0, t; }"
        : "=r"(a) : "l"(p));
    return a;
}
__device__ __forceinline__ void cp16(uint32_t dst, const void* src) {
    asm volatile("cp.async.cg.shared.global [%0], [%1], 16;" :: "r"(dst), "l"(src));
}
__device__ __forceinline__ void cp_commit() {
    asm volatile("cp.async.commit_group;" ::: "memory");
}
__device__ __forceinline__ void cp_wait0() { asm volatile("cp.async.wait_group 0;" ::: "memory"); }
__device__ __forceinline__ void cp_wait1() { asm volatile("cp.async.wait_group 1;" ::: "memory"); }
__device__ __forceinline__ void cp_wait2() { asm volatile("cp.async.wait_group 2;" ::: "memory"); }
__device__ __forceinline__ void mma1688(float* c, const uint32_t* a, const uint32_t* b) {
    asm volatile(
        "mma.sync.aligned.m16n8k8.row.col.f32.tf32.tf32.f32 "
        "{%0,%1,%2,%3}, {%4,%5,%6,%7}, {%8,%9}, {%0,%1,%2,%3};"
        : "+f"(c[0]), "+f"(c[1]), "+f"(c[2]), "+f"(c[3])
        : "r"(a[0]), "r"(a[1]), "r"(a[2]), "r"(a[3]), "r"(b[0]), "r"(b[1]));
}

// ---------------- prep: round to tf32 + frag-major scatter ------------------
__global__ __launch_bounds__(256) void prep_x(const float* __restrict__ x) {
    int row = blockIdx.x;
    int k0 = threadIdx.x * 4;
    float4 v = *(const float4*)&x[(size_t)row * DM + k0];
    float vv[4] = {tf32_rna(v.x), tf32_rna(v.y), tf32_rna(v.z), tf32_rna(v.w)};
    int base = ((row >> 4) * 128 + (k0 >> 3)) * 128;
    int s = 2 * ((k0 >> 2) & 1) + ((row >> 3) & 1);
    int l0 = (row & 7) * 4;
#pragma unroll
    for (int t = 0; t < 4; t++) g_xc[base + (l0 + t) * 4 + s] = vv[t];
}
__global__ __launch_bounds__(256) void prep_w(const float* __restrict__ w) {
    int b = blockIdx.x;
    int k = b / 3;
    int n0 = (b % 3) * 1024 + threadIdx.x * 4;
    float4 v = *(const float4*)&w[(size_t)k * NK + n0];
    float vv[4] = {tf32_rna(v.x), tf32_rna(v.y), tf32_rna(v.z), tf32_rna(v.w)};
    int base = ((n0 >> 3) * 64 + (k >> 4)) * 128;
    int s = ((k >> 3) & 1) * 2 + ((k >> 2) & 1);
    int lc = k & 3;
#pragma unroll
    for (int t = 0; t < 4; t++) {
        int n = n0 + t;
        g_wc[base + ((n & 7) * 4 + lc) * 4 + s] = vv[t];
    }
}

// ---------------- tf32 mma.sync KQV GEMM, 128x128 (R7 config) ---------------
#define GSTAGE_F 4096
#define GNSTAGES 4
#define GEMM_SMEM (GNSTAGES * GSTAGE_F * 4)

__device__ __forceinline__ void g_load_stage(uint32_t sb, int st, int kt16, int tid,
                                             int mt0, int n8b) {
    uint32_t ab = sb + st * (GSTAGE_F * 4);
    uint32_t bb = ab + 8192;
#pragma unroll
    for (int u = 0; u < 2; u++) {
        int c = tid + u * 256;
        int mti = c >> 6, rem = c & 63;
        int k8l = rem >> 5, cb = rem & 31;
        cp16(ab + ((mti * 2 + k8l) * 32 + cb) * 16,
             g_xc + (size_t)((mt0 + mti) * 128 + kt16 * 2 + k8l) * 128 + cb * 4);
    }
#pragma unroll
    for (int u = 0; u < 2; u++) {
        int c = tid + u * 256;
        int nt8l = c >> 5, cb = c & 31;
        cp16(bb + (nt8l * 32 + cb) * 16,
             g_wc + (size_t)((n8b + nt8l) * 64 + kt16) * 128 + cb * 4);
    }
}

__global__ __launch_bounds__(256) void kqv_gemm_mma() {
    extern __shared__ __align__(16) uint8_t smem_raw[];
    uint32_t sb = smem_u32(smem_raw);
    const int tid = threadIdx.x;
    const int warp = tid >> 5, lane = tid & 31;
    const int lr = lane >> 2, lc = lane & 3;
    const int wm = warp >> 1, wn = warp & 1;
    const int m0 = blockIdx.y * 128;
    const int n0 = blockIdx.x * 128;
    const int mt0 = blockIdx.y * 8;
    const int n8b = blockIdx.x * 16;

    float c[2][8][4];
#pragma unroll
    for (int i = 0; i < 2; i++)
#pragma unroll
        for (int j = 0; j < 8; j++)
#pragma unroll
            for (int t = 0; t < 4; t++) c[i][j][t] = 0.f;

#pragma unroll
    for (int s = 0; s < GNSTAGES - 1; s++) {
        g_load_stage(sb, s, s, tid, mt0, n8b);
        cp_commit();
    }
    cp_wait2();
    __syncthreads();

    for (int kt = 0; kt < 64; kt++) {
        int st = kt & (GNSTAGES - 1);
        const float* As = (const float*)(smem_raw + st * (GSTAGE_F * 4));
        const float* Bs = As + 2048;
        uint32_t a[2][2][4], b[8][4];
#pragma unroll
        for (int i = 0; i < 2; i++)
#pragma unroll
            for (int k8 = 0; k8 < 2; k8++) {
                const uint4 v = *(const uint4*)&As[((wm * 2 + i) * 2 + k8) * 128 + lane * 4];
                a[i][k8][0] = v.x; a[i][k8][1] = v.y; a[i][k8][2] = v.z; a[i][k8][3] = v.w;
            }
#pragma unroll
        for (int j = 0; j < 8; j++) {
            const uint4 v = *(const uint4*)&Bs[(wn * 8 + j) * 128 + lane * 4];
            b[j][0] = v.x; b[j][1] = v.y; b[j][2] = v.z; b[j][3] = v.w;
        }
#pragma unroll
        for (int k8 = 0; k8 < 2; k8++)
#pragma unroll
            for (int i = 0; i < 2; i++)
#pragma unroll
                for (int j = 0; j < 8; j++)
                    mma1688(c[i][j], a[i][k8], &b[j][k8 * 2]);
        __syncthreads();
        int nk = kt + GNSTAGES - 1;
        if (nk < 64) g_load_stage(sb, nk & (GNSTAGES - 1), nk, tid, mt0, n8b);
        cp_commit();
        cp_wait2();
        __syncthreads();
    }

    // ---- epilogue: scatter into frag-major g_q2/g_k2/g_v2 ----
    const int gc0 = n0 + wn * 64;
    const int chunk = gc0 >> 10;
    const int h = (gc0 & 1023) >> 6;
    const int mbase = m0 + wm * 32;

#pragma unroll
    for (int i = 0; i < 2; i++) {
#pragma unroll
        for (int j = 0; j < 8; j++) {
            float v0 = tf32_rna(c[i][j][0]), v1 = tf32_rna(c[i][j][1]);
            float v2 = tf32_rna(c[i][j][2]), v3 = tf32_rna(c[i][j][3]);
            int d = j * 8 + 2 * lc;
            int r = mbase + i * 16 + lr;
            if (chunk == 1) {                    // Q : a-frag
                int base = ((h * 256 + (r >> 4)) * 8 + j) * 128;
                int lp = lr * 4 + (d & 3);
                int k4 = (lc >> 1) & 1;
                *(float2*)&g_q2[base + lp * 4 + 2 * k4] = make_float2(v0, v2);
                *(float2*)&g_q2[base + (lp + 1) * 4 + 2 * k4] = make_float2(v1, v3);
            } else if (chunk == 0) {             // K : b-frag over d
                int d16 = j >> 1;
                int s = (j & 1) * 2 + (lc >> 1);
                int lp = lr * 4 + (d & 3);
                int ba = ((h * 512 + (r >> 3)) * 4 + d16) * 128;
                int bb = ((h * 512 + ((r + 8) >> 3)) * 4 + d16) * 128;
                g_k2[ba + lp * 4 + s] = v0;
                g_k2[ba + (lp + 1) * 4 + s] = v1;
                g_k2[bb + lp * 4 + s] = v2;
                g_k2[bb + (lp + 1) * 4 + s] = v3;
            } else {                             // V : b-frag transposed (k=keys)
#pragma unroll
                for (int rb = 0; rb < 2; rb++) {
                    int m = r + rb * 8;
                    float va = rb ? v2 : v0, vb = rb ? v3 : v1;
                    int base = (((h * 64 + (m >> 6)) * 8 + j) * 4 + ((m >> 4) & 3)) * 128;
                    int s = ((m >> 3) & 1) * 2 + ((m >> 2) & 1);
                    g_v2[base + ((d & 7) * 4 + (m & 3)) * 4 + s] = va;
                    g_v2[base + (((d + 1) & 7) * 4 + (m & 3)) * 4 + s] = vb;
                }
            }
        }
    }
}

// ---------------------------------------------------------------------------
// Tensor-core flash attention: 64 queries x 1 head per block, 4 warps.
// 2 blocks co-resident per SM -> cross-block latency hiding.
// ---------------------------------------------------------------------------
#define KV_OFF(s) ((s) * 8192)
#define P_OFF 16384
#define ATTN_SMEM ((16384 + 4096) * 4)     // 80 KB
#define SCL 0.03125f

__device__ __forceinline__ void a_load_kv(uint32_t sb, int s, int kt, int tid,
                                          const float* __restrict__ kb,
                                          const float* __restrict__ vb) {
    uint32_t kd = sb + KV_OFF(s) * 4;
    uint32_t vd = kd + 4096 * 4;
    const float* kg = kb + (size_t)kt * 4096;
    const float* vg = vb + (size_t)kt * 4096;
#pragma unroll
    for (int u = 0; u < 8; u++) {
        int c = tid + u * 128;
        cp16(kd + c * 16, kg + c * 4);
        cp16(vd + c * 16, vg + c * 4);
    }
}

__global__ __launch_bounds__(128, 2) void attn_tc(float* __restrict__ out) {
    extern __shared__ __align__(16) uint8_t smem_raw[];
    float* sm = (float*)smem_raw;
    uint32_t sb = smem_u32(smem_raw);

    const int tid = threadIdx.x;
    const int w = tid >> 5, lane = tid & 31;
    const int lr = lane >> 2, lc = lane & 3;
    const int qt = blockIdx.x;          // 0..63 (64-query tiles)
    const int h = blockIdx.y;
    const int q0 = qt * 64;

    const float slope = exp2f(-0.5f * (float)(h + 1));
    const float* __restrict__ kbh = g_k2 + (size_t)h * S * HD;
    const float* __restrict__ vbh = g_v2 + (size_t)h * S * HD;

    const int kt0 = (qt >= 8) ? (qt - 8) : 0;
    const int kt1 = qt;

    a_load_kv(sb, 0, kt0, tid, kbh, vbh);
    cp_commit();

    // Q fragments straight from gmem (coalesced LDG.128); warp's mt = qt*4+w
    uint32_t qa[8][4];
    {
        const float* qb = g_q2 + (size_t)((h * 256 + qt * 4 + w) * 8) * 128;
#pragma unroll
        for (int k8 = 0; k8 < 8; k8++) {
            uint4 v = *(const uint4*)&qb[k8 * 128 + lane * 4];
            qa[k8][0] = v.x; qa[k8][1] = v.y; qa[k8][2] = v.z; qa[k8][3] = v.w;
        }
    }

    float o[8][4];
    float m0r = -1e30f, m1r = -1e30f, l0 = 0.f, l1 = 0.f;
#pragma unroll
    for (int nt = 0; nt < 8; nt++)
#pragma unroll
        for (int t = 0; t < 4; t++) o[nt][t] = 0.f;

    const int i0 = q0 + w * 16 + lr;
    const int i1 = i0 + 8;
    float* Pw = sm + P_OFF + w * 1024;
    const float s8 = slope * 8.f;

    for (int kt = kt0; kt <= kt1; kt++) {
        int st = (kt - kt0) & 1;
        if (kt < kt1) {
            a_load_kv(sb, st ^ 1, kt + 1, tid, kbh, vbh);
            cp_commit();
            cp_wait1();
        } else {
            cp_wait0();
        }
        __syncthreads();

        const float* Ks = sm + KV_OFF(st);
        const float* Vs = Ks + 4096;
        const int kb = kt * 64;

        // ---- S = Q K^T ----
        float sc[8][4];
#pragma unroll
        for (int nt = 0; nt < 8; nt++)
#pragma unroll
            for (int t = 0; t < 4; t++) sc[nt][t] = 0.f;
#pragma unroll
        for (int k16 = 0; k16 < 4; k16++) {
            uint32_t bk[8][4];
#pragma unroll
            for (int nt = 0; nt < 8; nt++) {
                uint4 v = *(const uint4*)&Ks[(nt * 4 + k16) * 128 + lane * 4];
                bk[nt][0] = v.x; bk[nt][1] = v.y; bk[nt][2] = v.z; bk[nt][3] = v.w;
            }
#pragma unroll
            for (int nt = 0; nt < 8; nt++) mma1688(sc[nt], qa[k16 * 2], &bk[nt][0]);
#pragma unroll
            for (int nt = 0; nt < 8; nt++) mma1688(sc[nt], qa[k16 * 2 + 1], &bk[nt][2]);
        }

        // ---- bias/mask + online softmax ----
        const bool full = (kt >= qt - 7) && (kt <= qt - 1);
        float mx0 = -3e38f, mx1 = -3e38f;
        if (full) {
            float bias = slope * (float)(kb + 2 * lc - i0);
#pragma unroll
            for (int nt = 0; nt < 8; nt++) {
                sc[nt][0] = fmaf(sc[nt][0], SCL, bias);
                sc[nt][1] = fmaf(sc[nt][1], SCL, bias + slope);
                sc[nt][2] = fmaf(sc[nt][2], SCL, bias - s8);
                sc[nt][3] = fmaf(sc[nt][3], SCL, bias - s8 + slope);
                mx0 = fmaxf(mx0, fmaxf(sc[nt][0], sc[nt][1]));
                mx1 = fmaxf(mx1, fmaxf(sc[nt][2], sc[nt][3]));
                bias += s8;
            }
        } else {
#pragma unroll
            for (int nt = 0; nt < 8; nt++) {
                int j0 = kb + nt * 8 + 2 * lc;
                int d00 = i0 - j0;
                sc[nt][0] = (d00 >= 0 && d00 <= WIN)
                                ? fmaf(sc[nt][0], SCL, slope * (float)(-d00)) : -3e38f;
                int d01 = d00 - 1;
                sc[nt][1] = (d01 >= 0 && d01 <= WIN)
                                ? fmaf(sc[nt][1], SCL, slope * (float)(-d01)) : -3e38f;
                int d10 = i1 - j0;
                sc[nt][2] = (d10 >= 0 && d10 <= WIN)
                                ? fmaf(sc[nt][2], SCL, slope * (float)(-d10)) : -3e38f;
                int d11 = d10 - 1;
                sc[nt][3] = (d11 >= 0 && d11 <= WIN)
                                ? fmaf(sc[nt][3], SCL, slope * (float)(-d11)) : -3e38f;
                mx0 = fmaxf(mx0, fmaxf(sc[nt][0], sc[nt][1]));
                mx1 = fmaxf(mx1, fmaxf(sc[nt][2], sc[nt][3]));
            }
        }
        mx0 = fmaxf(mx0, __shfl_xor_sync(0xffffffffu, mx0, 1));
        mx0 = fmaxf(mx0, __shfl_xor_sync(0xffffffffu, mx0, 2));
        mx1 = fmaxf(mx1, __shfl_xor_sync(0xffffffffu, mx1, 1));
        mx1 = fmaxf(mx1, __shfl_xor_sync(0xffffffffu, mx1, 2));

        float mn0 = fmaxf(m0r, mx0), mn1 = fmaxf(m1r, mx1);
        float al0 = __expf(m0r - mn0), al1 = __expf(m1r - mn1);
        m0r = mn0; m1r = mn1;

        const int lp = lr * 4 + ((2 * lc) & 3);
        const int k4b = 2 * ((lc >> 1) & 1);
        float rs0 = 0.f, rs1 = 0.f;
#pragma unroll
        for (int nt = 0; nt < 8; nt++) {
            float p00 = tf32_rna(__expf(sc[nt][0] - mn0));
            float p01 = tf32_rna(__expf(sc[nt][1] - mn0));
            float p10 = tf32_rna(__expf(sc[nt][2] - mn1));
            float p11 = tf32_rna(__expf(sc[nt][3] - mn1));
            rs0 += p00 + p01;
            rs1 += p10 + p11;
            *(float2*)&Pw[nt * 128 + lp * 4 + k4b] = make_float2(p00, p10);
            *(float2*)&Pw[nt * 128 + (lp + 1) * 4 + k4b] = make_float2(p01, p11);
        }
        rs0 += __shfl_xor_sync(0xffffffffu, rs0, 1);
        rs0 += __shfl_xor_sync(0xffffffffu, rs0, 2);
        rs1 += __shfl_xor_sync(0xffffffffu, rs1, 1);
        rs1 += __shfl_xor_sync(0xffffffffu, rs1, 2);
        l0 = l0 * al0 + rs0;
        l1 = l1 * al1 + rs1;
#pragma unroll
        for (int nt = 0; nt < 8; nt++) {
            o[nt][0] *= al0; o[nt][1] *= al0;
            o[nt][2] *= al1; o[nt][3] *= al1;
        }
        __syncwarp();

        uint32_t pa[8][4];
#pragma unroll
        for (int k8 = 0; k8 < 8; k8++) {
            uint4 v = *(const uint4*)&Pw[k8 * 128 + lane * 4];
            pa[k8][0] = v.x; pa[k8][1] = v.y; pa[k8][2] = v.z; pa[k8][3] = v.w;
        }

        // ---- O += P V ----
#pragma unroll
        for (int k16 = 0; k16 < 4; k16++) {
            uint32_t vk[8][4];
#pragma unroll
            for (int nt = 0; nt < 8; nt++) {
                uint4 v = *(const uint4*)&Vs[(nt * 4 + k16) * 128 + lane * 4];
                vk[nt][0] = v.x; vk[nt][1] = v.y; vk[nt][2] = v.z; vk[nt][3] = v.w;
            }
#pragma unroll
            for (int nt = 0; nt < 8; nt++) mma1688(o[nt], pa[k16 * 2], &vk[nt][0]);
#pragma unroll
            for (int nt = 0; nt < 8; nt++) mma1688(o[nt], pa[k16 * 2 + 1], &vk[nt][2]);
        }
        __syncthreads();
    }

    // ---- normalize + write ----
    float inv0 = 1.f / l0, inv1 = 1.f / l1;
    float* o0 = out + (size_t)i0 * DM + h * HD;
    float* o1 = out + (size_t)i1 * DM + h * HD;
#pragma unroll
    for (int nt = 0; nt < 8; nt++) {
        *(float2*)&o0[nt * 8 + 2 * lc] = make_float2(o[nt][0] * inv0, o[nt][1] * inv0);
        *(float2*)&o1[nt * 8 + 2 * lc] = make_float2(o[nt][2] * inv1, o[nt][3] * inv1);
    }
}

// ---------------------------------------------------------------------------
extern "C" void kernel_launch(void* const* d_in, const int* in_sizes, int n_in,
                              void* d_out, int out_size) {
    const float* x = (const float*)d_in[0];
    const float* w = (const float*)d_in[1];
    if (n_in >= 2 && in_sizes[0] == DM * NK && in_sizes[1] == S * DM) {
        const float* t = x; x = w; w = t;
    }
    float* out = (float*)d_out;

    static int attr_set = 0;
    if (!attr_set) {
        cudaFuncSetAttribute(kqv_gemm_mma, cudaFuncAttributeMaxDynamicSharedMemorySize,
                             GEMM_SMEM);
        cudaFuncSetAttribute(attn_tc, cudaFuncAttributeMaxDynamicSharedMemorySize,
                             ATTN_SMEM);
        attr_set = 1;
    }

    prep_x<<<4096, 256>>>(x);
    prep_w<<<3072, 256>>>(w);

    dim3 ggrid(NK / 128, S / 128);       // 24 x 32
    kqv_gemm_mma<<<ggrid, 256, GEMM_SMEM>>>();

    dim3 agrid(S / 64, H);               // 64 x 16 blocks, 128 thr
    attn_tc<<<agrid, 128, ATTN_SMEM>>>(out);
}

// round 11
// speedup vs baseline: 2.2676x; 2.0558x over previous
#include <cuda_runtime.h>
#include <cuda_fp16.h>
#include <cstdint>

#define S 4096
#define DM 1024
#define H 16
#define HD 64
#define WIN 512
#define NK 3072

// ---------------- device scratch (fp16 frag-major layouts, u32 = half2) ----
// g_xc : a-frag [mt(256)][k16(64)][lane][4]      (KQV GEMM A = x)
// g_wc : b-frag [nt8(384)][k16(64)][lane][2]     (KQV GEMM B = w)
// g_q2 : a-frag [h][mt(256)][d16(4)][lane][4]    (QK A, k-dim = d)
// g_k2 : b-frag [h][nt8(512)][d16(4)][lane][2]   (QK B, n = keys, k = d)
// g_v2 : b-frag [h][t(64)][dt8(8)][k16(4)][lane][2] (PV B, n = d, k = keys)
__device__ uint32_t g_xc[S * DM / 2];
__device__ uint32_t g_wc[DM * NK / 2];
__device__ uint32_t g_q2[H * S * HD / 2];
__device__ uint32_t g_k2[H * S * HD / 2];
__device__ uint32_t g_v2[H * S * HD / 2];

// ---------------- helpers ---------------------------------------------------
__device__ __forceinline__ uint32_t h2(float lo, float hi) {
    half2 h = __floats2half2_rn(lo, hi);   // .x = lo
    return *(uint32_t*)&h;
}
__device__ __forceinline__ uint32_t smem_u32(const void* p) {
    uint32_t a;
    asm("{ .reg .u64 t; cvta.to.shared.u64 t, %1; cvt.u32.u64 %0, t; }"
        : "=r"(a) : "l"(p));
    return a;
}
__device__ __forceinline__ void cp16(uint32_t dst, const void* src) {
    asm volatile("cp.async.cg.shared.global [%0], [%1], 16;" :: "r"(dst), "l"(src));
}
__device__ __forceinline__ void cp_commit() {
    asm volatile("cp.async.commit_group;" ::: "memory");
}
__device__ __forceinline__ void cp_wait0() { asm volatile("cp.async.wait_group 0;" ::: "memory"); }
__device__ __forceinline__ void cp_wait1() { asm volatile("cp.async.wait_group 1;" ::: "memory"); }
__device__ __forceinline__ void cp_wait2() { asm volatile("cp.async.wait_group 2;" ::: "memory"); }
// D += A*B : m16n8k16 fp16 in, fp32 accum
__device__ __forceinline__ void mma16816(float* c, const uint32_t* a, const uint32_t* b) {
    asm volatile(
        "mma.sync.aligned.m16n8k16.row.col.f32.f16.f16.f32 "
        "{%0,%1,%2,%3}, {%4,%5,%6,%7}, {%8,%9}, {%0,%1,%2,%3};"
        : "+f"(c[0]), "+f"(c[1]), "+f"(c[2]), "+f"(c[3])
        : "r"(a[0]), "r"(a[1]), "r"(a[2]), "r"(a[3]), "r"(b[0]), "r"(b[1]));
}

// ---------------- prep: fp16 convert + frag-major scatter -------------------
__global__ __launch_bounds__(256) void prep_x(const float* __restrict__ x) {
    int row = blockIdx.x;
    int k0 = threadIdx.x * 4;
    float4 v = *(const float4*)&x[(size_t)row * DM + k0];
    uint32_t ha = h2(v.x, v.y);             // (k0, k0+1)
    uint32_t hb = h2(v.z, v.w);             // (k0+2, k0+3)
    int base = ((row >> 4) * 64 + (k0 >> 4)) * 128;
    int r = ((row >> 3) & 1) + 2 * ((k0 >> 3) & 1);
    int lane = (row & 7) * 4 + ((k0 & 7) >> 1);
    g_xc[base + lane * 4 + r] = ha;
    g_xc[base + (lane + 1) * 4 + r] = hb;
}
__global__ __launch_bounds__(256) void prep_w(const float* __restrict__ w) {
    int g = blockIdx.x * 256 + threadIdx.x;   // 393216 threads
    int k0 = 2 * (g / 768);
    int n0 = 4 * (g % 768);
    float4 v0 = *(const float4*)&w[(size_t)k0 * NK + n0];
    float4 v1 = *(const float4*)&w[(size_t)(k0 + 1) * NK + n0];
    float a0[4] = {v0.x, v0.y, v0.z, v0.w};
    float a1[4] = {v1.x, v1.y, v1.z, v1.w};
    int k16 = k0 >> 4;
    int lcp = (k0 & 7) >> 1;
    int reg = (k0 >> 3) & 1;
#pragma unroll
    for (int t = 0; t < 4; t++) {
        int n = n0 + t;
        g_wc[((n >> 3) * 64 + k16) * 64 + ((n & 7) * 4 + lcp) * 2 + reg] = h2(a0[t], a1[t]);
    }
}

// ---------------- fp16 KQV GEMM: 128x128, BK=32, 4 stages -------------------
#define GSTAGE_U 4096                         // u32 per stage (A 2048 + B 2048)
#define GNSTAGES 4
#define GEMM_SMEM (GNSTAGES * GSTAGE_U * 4)   // 64 KB

__device__ __forceinline__ void g_load_stage(uint32_t sb, int st, int kt, int tid,
                                             int mt0, int n8b) {
    uint32_t ab = sb + st * (GSTAGE_U * 4);
    uint32_t bb = ab + 2048 * 4;
#pragma unroll
    for (int u = 0; u < 2; u++) {                  // A: 512 uint4
        int c = tid + u * 256;
        int blk = c >> 5, cb = c & 31;             // 16 blocks = 8mt x 2k16
        cp16(ab + (blk * 32 + cb) * 16,
             g_xc + (size_t)((mt0 + (blk >> 1)) * 64 + kt * 2 + (blk & 1)) * 128 + cb * 4);
    }
#pragma unroll
    for (int u = 0; u < 2; u++) {                  // B: 512 uint4
        int c = tid + u * 256;
        int blk = c >> 4, cb = c & 15;             // 32 blocks = 16nt8 x 2k16
        cp16(bb + (blk * 16 + cb) * 16,
             g_wc + (size_t)((n8b + (blk >> 1)) * 64 + kt * 2 + (blk & 1)) * 64 + cb * 4);
    }
}

__global__ __launch_bounds__(256) void kqv_gemm_mma() {
    extern __shared__ __align__(16) uint8_t smem_raw[];
    uint32_t sb = smem_u32(smem_raw);
    const int tid = threadIdx.x;
    const int warp = tid >> 5, lane = tid & 31;
    const int lr = lane >> 2, lc = lane & 3;
    const int wm = warp >> 1, wn = warp & 1;
    const int m0 = blockIdx.y * 128;
    const int n0 = blockIdx.x * 128;
    const int mt0 = blockIdx.y * 8;
    const int n8b = blockIdx.x * 16;

    float c[2][8][4];
#pragma unroll
    for (int i = 0; i < 2; i++)
#pragma unroll
        for (int j = 0; j < 8; j++)
#pragma unroll
            for (int t = 0; t < 4; t++) c[i][j][t] = 0.f;

#pragma unroll
    for (int s = 0; s < GNSTAGES - 1; s++) {
        g_load_stage(sb, s, s, tid, mt0, n8b);
        cp_commit();
    }
    cp_wait2();
    __syncthreads();

    for (int kt = 0; kt < 32; kt++) {
        int st = kt & (GNSTAGES - 1);
        const uint32_t* As = (const uint32_t*)(smem_raw + st * (GSTAGE_U * 4));
        const uint32_t* Bs = As + 2048;
        uint32_t a[2][2][4], b[8][2][2];
#pragma unroll
        for (int i = 0; i < 2; i++)
#pragma unroll
            for (int kk = 0; kk < 2; kk++) {
                uint4 v = *(const uint4*)&As[((wm * 2 + i) * 2 + kk) * 128 + lane * 4];
                a[i][kk][0] = v.x; a[i][kk][1] = v.y; a[i][kk][2] = v.z; a[i][kk][3] = v.w;
            }
#pragma unroll
        for (int j = 0; j < 8; j++)
#pragma unroll
            for (int kk = 0; kk < 2; kk++) {
                uint2 v = *(const uint2*)&Bs[((wn * 8 + j) * 2 + kk) * 64 + lane * 2];
                b[j][kk][0] = v.x; b[j][kk][1] = v.y;
            }
#pragma unroll
        for (int kk = 0; kk < 2; kk++)
#pragma unroll
            for (int i = 0; i < 2; i++)
#pragma unroll
                for (int j = 0; j < 8; j++)
                    mma16816(c[i][j], a[i][kk], b[j][kk]);
        __syncthreads();
        int nk = kt + GNSTAGES - 1;
        if (nk < 32) g_load_stage(sb, nk & (GNSTAGES - 1), nk, tid, mt0, n8b);
        cp_commit();
        cp_wait2();
        __syncthreads();
    }

    // ---- epilogue: fp16 scatter into g_q2/g_k2/g_v2 ----
    const int gc0 = n0 + wn * 64;
    const int chunk = gc0 >> 10;
    const int h = (gc0 & 1023) >> 6;
    const int mbase = m0 + wm * 32;

#pragma unroll
    for (int i = 0; i < 2; i++) {
#pragma unroll
        for (int j = 0; j < 8; j++) {
            float v0 = c[i][j][0], v1 = c[i][j][1], v2 = c[i][j][2], v3 = c[i][j][3];
            int r = mbase + i * 16 + lr;          // rows r, r+8
            if (chunk == 1) {                     // Q : a-frag over d
                int base = ((h * 256 + (r >> 4)) * 4 + (j >> 1)) * 128
                           + (lr * 4 + lc) * 4 + 2 * (j & 1);
                g_q2[base + 0] = h2(v0, v1);      // row r,  k-low pair
                g_q2[base + 1] = h2(v2, v3);      // row r+8
            } else if (chunk == 0) {              // K : b-frag, n=keys, k=d
                int d16 = j >> 1, reg = j & 1;
                int lo = (lr * 4 + lc) * 2 + reg;
                g_k2[((h * 512 + (r >> 3)) * 4 + d16) * 64 + lo] = h2(v0, v1);
                g_k2[((h * 512 + ((r + 8) >> 3)) * 4 + d16) * 64 + lo] = h2(v2, v3);
            } else {                              // V : b-frag, n=d, k=keys
                half* gv = (half*)g_v2;
#pragma unroll
                for (int rb = 0; rb < 2; rb++) {
                    int m = r + rb * 8;
                    float va = rb ? v2 : v0, vb = rb ? v3 : v1;
                    int blk = (((h * 64 + (m >> 6)) * 8 + j) * 4 + ((m >> 4) & 3)) * 128;
                    int sub = ((m >> 3) & 1) * 2 + (m & 1);
                    int d0 = 2 * lc;
                    gv[blk + (d0 * 4 + ((m & 7) >> 1)) * 4 + sub] = __float2half_rn(va);
                    gv[blk + ((d0 + 1) * 4 + ((m & 7) >> 1)) * 4 + sub] = __float2half_rn(vb);
                }
            }
        }
    }
}

// ---------------------------------------------------------------------------
// fp16 tensor-core flash attention: 64 queries x head, 4 warps, 3 blocks/SM.
// P converts to PV A-fragments IN REGISTERS (no smem round-trip).
// ---------------------------------------------------------------------------
#define KV_U(s) ((s) * 4096)                 // u32 per stage: K 2048 + V 2048
#define ATTN_SMEM (2 * 4096 * 4)             // 32 KB
#define SCL 0.03125f

__device__ __forceinline__ void a_load_kv(uint32_t sb, int s, int kt, int tid,
                                          const uint32_t* __restrict__ kb,
                                          const uint32_t* __restrict__ vb) {
    uint32_t kd = sb + KV_U(s) * 4;
    uint32_t vd = kd + 2048 * 4;
    const uint32_t* kg = kb + (size_t)kt * 2048;
    const uint32_t* vg = vb + (size_t)kt * 2048;
#pragma unroll
    for (int u = 0; u < 4; u++) {
        int c = tid + u * 128;                // 512 uint4 each
        cp16(kd + c * 16, kg + c * 4);
        cp16(vd + c * 16, vg + c * 4);
    }
}

__global__ __launch_bounds__(128, 3) void attn_tc(float* __restrict__ out) {
    extern __shared__ __align__(16) uint8_t smem_raw[];
    uint32_t* smu = (uint32_t*)smem_raw;
    uint32_t sb = smem_u32(smem_raw);

    const int tid = threadIdx.x;
    const int w = tid >> 5, lane = tid & 31;
    const int lr = lane >> 2, lc = lane & 3;
    const int qt = blockIdx.x;                // 64-query tiles
    const int h = blockIdx.y;
    const int q0 = qt * 64;

    const float slope = exp2f(-0.5f * (float)(h + 1));
    const uint32_t* __restrict__ kbh = g_k2 + (size_t)h * 512 * 256;
    const uint32_t* __restrict__ vbh = g_v2 + (size_t)h * 64 * 2048;

    const int kt0 = (qt >= 8) ? (qt - 8) : 0;
    const int kt1 = qt;

    a_load_kv(sb, 0, kt0, tid, kbh, vbh);
    cp_commit();

    // Q a-fragments from gmem (coalesced LDG.128)
    uint32_t qa[4][4];
    {
        const uint32_t* qb = g_q2 + (size_t)((h * 256 + qt * 4 + w) * 4) * 128;
#pragma unroll
        for (int d16 = 0; d16 < 4; d16++) {
            uint4 v = *(const uint4*)&qb[d16 * 128 + lane * 4];
            qa[d16][0] = v.x; qa[d16][1] = v.y; qa[d16][2] = v.z; qa[d16][3] = v.w;
        }
    }

    float o[8][4];
    float m0r = -1e30f, m1r = -1e30f, l0 = 0.f, l1 = 0.f;
#pragma unroll
    for (int dt = 0; dt < 8; dt++)
#pragma unroll
        for (int t = 0; t < 4; t++) o[dt][t] = 0.f;

    const int i0 = q0 + w * 16 + lr;
    const int i1 = i0 + 8;
    const float s8 = slope * 8.f;

    for (int kt = kt0; kt <= kt1; kt++) {
        int st = (kt - kt0) & 1;
        if (kt < kt1) {
            a_load_kv(sb, st ^ 1, kt + 1, tid, kbh, vbh);
            cp_commit();
            cp_wait1();
        } else {
            cp_wait0();
        }
        __syncthreads();

        const uint32_t* Ks = smu + KV_U(st);
        const uint32_t* Vs = Ks + 2048;
        const int kb = kt * 64;

        // ---- S = Q K^T ----
        float sc[8][4];
#pragma unroll
        for (int nt = 0; nt < 8; nt++)
#pragma unroll
            for (int t = 0; t < 4; t++) sc[nt][t] = 0.f;
#pragma unroll
        for (int d16 = 0; d16 < 4; d16++) {
            uint32_t bk[8][2];
#pragma unroll
            for (int nt = 0; nt < 8; nt++) {
                uint2 v = *(const uint2*)&Ks[(nt * 4 + d16) * 64 + lane * 2];
                bk[nt][0] = v.x; bk[nt][1] = v.y;
            }
#pragma unroll
            for (int nt = 0; nt < 8; nt++) mma16816(sc[nt], qa[d16], bk[nt]);
        }

        // ---- bias/mask + online softmax ----
        const bool full = (kt >= qt - 7) && (kt <= qt - 1);
        float mx0 = -3e38f, mx1 = -3e38f;
        if (full) {
            float bias = slope * (float)(kb + 2 * lc - i0);
#pragma unroll
            for (int nt = 0; nt < 8; nt++) {
                sc[nt][0] = fmaf(sc[nt][0], SCL, bias);
                sc[nt][1] = fmaf(sc[nt][1], SCL, bias + slope);
                sc[nt][2] = fmaf(sc[nt][2], SCL, bias - s8);
                sc[nt][3] = fmaf(sc[nt][3], SCL, bias - s8 + slope);
                mx0 = fmaxf(mx0, fmaxf(sc[nt][0], sc[nt][1]));
                mx1 = fmaxf(mx1, fmaxf(sc[nt][2], sc[nt][3]));
                bias += s8;
            }
        } else {
#pragma unroll
            for (int nt = 0; nt < 8; nt++) {
                int j0 = kb + nt * 8 + 2 * lc;
                int d00 = i0 - j0;
                sc[nt][0] = (d00 >= 0 && d00 <= WIN)
                                ? fmaf(sc[nt][0], SCL, slope * (float)(-d00)) : -3e38f;
                int d01 = d00 - 1;
                sc[nt][1] = (d01 >= 0 && d01 <= WIN)
                                ? fmaf(sc[nt][1], SCL, slope * (float)(-d01)) : -3e38f;
                int d10 = i1 - j0;
                sc[nt][2] = (d10 >= 0 && d10 <= WIN)
                                ? fmaf(sc[nt][2], SCL, slope * (float)(-d10)) : -3e38f;
                int d11 = d10 - 1;
                sc[nt][3] = (d11 >= 0 && d11 <= WIN)
                                ? fmaf(sc[nt][3], SCL, slope * (float)(-d11)) : -3e38f;
                mx0 = fmaxf(mx0, fmaxf(sc[nt][0], sc[nt][1]));
                mx1 = fmaxf(mx1, fmaxf(sc[nt][2], sc[nt][3]));
            }
        }
        mx0 = fmaxf(mx0, __shfl_xor_sync(0xffffffffu, mx0, 1));
        mx0 = fmaxf(mx0, __shfl_xor_sync(0xffffffffu, mx0, 2));
        mx1 = fmaxf(mx1, __shfl_xor_sync(0xffffffffu, mx1, 1));
        mx1 = fmaxf(mx1, __shfl_xor_sync(0xffffffffu, mx1, 2));

        float mn0 = fmaxf(m0r, mx0), mn1 = fmaxf(m1r, mx1);
        float al0 = __expf(m0r - mn0), al1 = __expf(m1r - mn1);
        m0r = mn0; m1r = mn1;

        // ---- exp + row-sum + in-register P a-frags ----
        uint32_t pa[4][4];
        float rs0 = 0.f, rs1 = 0.f;
#pragma unroll
        for (int nt = 0; nt < 8; nt++) {
            float p00 = __expf(sc[nt][0] - mn0);
            float p01 = __expf(sc[nt][1] - mn0);
            float p10 = __expf(sc[nt][2] - mn1);
            float p11 = __expf(sc[nt][3] - mn1);
            rs0 += p00 + p01;
            rs1 += p10 + p11;
            pa[nt >> 1][(nt & 1) * 2 + 0] = h2(p00, p01);   // row lr
            pa[nt >> 1][(nt & 1) * 2 + 1] = h2(p10, p11);   // row lr+8
        }
        rs0 += __shfl_xor_sync(0xffffffffu, rs0, 1);
        rs0 += __shfl_xor_sync(0xffffffffu, rs0, 2);
        rs1 += __shfl_xor_sync(0xffffffffu, rs1, 1);
        rs1 += __shfl_xor_sync(0xffffffffu, rs1, 2);
        l0 = l0 * al0 + rs0;
        l1 = l1 * al1 + rs1;
#pragma unroll
        for (int dt = 0; dt < 8; dt++) {
            o[dt][0] *= al0; o[dt][1] *= al0;
            o[dt][2] *= al1; o[dt][3] *= al1;
        }

        // ---- O += P V ----
#pragma unroll
        for (int k16 = 0; k16 < 4; k16++) {
            uint32_t vk[8][2];
#pragma unroll
            for (int dt = 0; dt < 8; dt++) {
                uint2 v = *(const uint2*)&Vs[(dt * 4 + k16) * 64 + lane * 2];
                vk[dt][0] = v.x; vk[dt][1] = v.y;
            }
#pragma unroll
            for (int dt = 0; dt < 8; dt++) mma16816(o[dt], pa[k16], vk[dt]);
        }
        __syncthreads();
    }

    // ---- normalize + write ----
    float inv0 = 1.f / l0, inv1 = 1.f / l1;
    float* o0 = out + (size_t)i0 * DM + h * HD;
    float* o1 = out + (size_t)i1 * DM + h * HD;
#pragma unroll
    for (int dt = 0; dt < 8; dt++) {
        *(float2*)&o0[dt * 8 + 2 * lc] = make_float2(o[dt][0] * inv0, o[dt][1] * inv0);
        *(float2*)&o1[dt * 8 + 2 * lc] = make_float2(o[dt][2] * inv1, o[dt][3] * inv1);
    }
}

// ---------------------------------------------------------------------------
extern "C" void kernel_launch(void* const* d_in, const int* in_sizes, int n_in,
                              void* d_out, int out_size) {
    const float* x = (const float*)d_in[0];
    const float* w = (const float*)d_in[1];
    if (n_in >= 2 && in_sizes[0] == DM * NK && in_sizes[1] == S * DM) {
        const float* t = x; x = w; w = t;
    }
    float* out = (float*)d_out;

    static int attr_set = 0;
    if (!attr_set) {
        cudaFuncSetAttribute(kqv_gemm_mma, cudaFuncAttributeMaxDynamicSharedMemorySize,
                             GEMM_SMEM);
        cudaFuncSetAttribute(attn_tc, cudaFuncAttributeMaxDynamicSharedMemorySize,
                             ATTN_SMEM);
        attr_set = 1;
    }

    prep_x<<<4096, 256>>>(x);
    prep_w<<<1536, 256>>>(w);

    dim3 ggrid(NK / 128, S / 128);       // 24 x 32
    kqv_gemm_mma<<<ggrid, 256, GEMM_SMEM>>>();

    dim3 agrid(S / 64, H);               // 64 x 16, 128 thr
    attn_tc<<<agrid, 128, ATTN_SMEM>>>(out);
}